// round 12
// baseline (speedup 1.0000x reference)
#include <cuda_runtime.h>
#include <cuda_bf16.h>
#include <math.h>

#define H    850
#define H2   1700
#define BB   256
#define TT   128
#define BH   (BB*H)
#define SP   896
#define NIT  28
#define NSTG 4
#define JPS  508          // jobs per step: 9*56 GEMM tiles + 4 mean jobs

__device__ float g_W0x[H*H2];
__device__ __nv_bfloat16 g_Wt[9][1792*896];   // fused weights, bf16, [n][k]
__device__ float g_XW[(size_t)TT*BB*H2];
__device__ float g_S[9][BB*SP];
__device__ __nv_bfloat16 g_Sb[9][BB*SP];
__device__ float g_Hprev[BB*SP];
__device__ __nv_bfloat16 g_Hb[BB*SP];

__device__ unsigned g_cnt8[8*32];
__device__ unsigned g_master;
__device__ volatile unsigned g_gen;
__device__ unsigned g_ticket;
__device__ unsigned g_done[9][4];    // [state][m_block] tile-completion counters
__device__ unsigned g_mdone[4];      // mean completion per m_block

__device__ __forceinline__ unsigned tf32(float x) {
    unsigned r; asm("cvt.rna.tf32.f32 %0, %1;" : "=r"(r) : "f"(x)); return r;
}
__device__ __forceinline__ void mma8(float* d, const unsigned* a, const unsigned* b) {
    asm("mma.sync.aligned.m16n8k8.row.col.f32.tf32.tf32.f32 "
        "{%0,%1,%2,%3}, {%4,%5,%6,%7}, {%8,%9}, {%0,%1,%2,%3};"
        : "+f"(d[0]), "+f"(d[1]), "+f"(d[2]), "+f"(d[3])
        : "r"(a[0]), "r"(a[1]), "r"(a[2]), "r"(a[3]), "r"(b[0]), "r"(b[1]));
}
__device__ __forceinline__ void mma16(float* d, const unsigned* a, const unsigned* b) {
    asm("mma.sync.aligned.m16n8k16.row.col.f32.bf16.bf16.f32 "
        "{%0,%1,%2,%3}, {%4,%5,%6,%7}, {%8,%9}, {%0,%1,%2,%3};"
        : "+f"(d[0]), "+f"(d[1]), "+f"(d[2]), "+f"(d[3])
        : "r"(a[0]), "r"(a[1]), "r"(a[2]), "r"(a[3]), "r"(b[0]), "r"(b[1]));
}
__device__ __forceinline__ void cp16(void* dst, const void* src) {
    unsigned u = (unsigned)__cvta_generic_to_shared(dst);
    asm volatile("cp.async.cg.shared.global [%0], [%1], 16;" :: "r"(u), "l"(src));
}

#define ACT_TANH 0
#define ACT_RELU 1
#define ACT_SIG  2
#define ACT_ID   3
__device__ __forceinline__ float apply_act(float x, int a) {
    switch (a) {
        case ACT_TANH: return tanhf(x);
        case ACT_RELU: return fmaxf(x, 0.f);
        case ACT_SIG:  return 1.f / (1.f + expf(-x));
        default:       return x;
    }
}
__device__ __forceinline__ float sigf(float x) { return 1.f / (1.f + expf(-x)); }

// ---- tf32 weight fusion; writes g_W0x (fp32) and g_Wt (bf16 [n][k]) ----
__global__ void __launch_bounds__(256) fuse_mma(
    int mode, const float* __restrict__ A, const float* __restrict__ Sig,
    const float* __restrict__ Bx)
{
    __shared__ unsigned As[128][17];
    __shared__ unsigned Bs[16][65];

    int z = blockIdx.z;
    int M = mode ? H : H2;
    int K = M, lda = M;
    const float* Ap = A;
    const float* Sp = Sig;
    const float* Bp = Bx;
    if (mode == 1) { Ap = A + (size_t)z*H*H; Sp = Sig + z*H; Bp = Bx + (size_t)z*H2*H2; }

    int tid = threadIdx.x;
    int w = tid >> 5, lane = tid & 31;
    int g = lane >> 2, c = lane & 3;
    int wm = (w & 3) * 32, wn = (w >> 2) * 32;
    int m0 = blockIdx.y << 7, n0 = blockIdx.x << 6;

    float acc[2][4][4];
    #pragma unroll
    for (int i = 0; i < 2; i++)
        #pragma unroll
        for (int j = 0; j < 4; j++)
            #pragma unroll
            for (int r = 0; r < 4; r++) acc[i][j][r] = 0.f;

    for (int kt = 0; kt < K; kt += 16) {
        #pragma unroll
        for (int i = 0; i < 8; i++) {
            int idx = tid + (i << 8);
            int am = idx >> 4, ak = idx & 15;
            int gm = m0 + am, gk = kt + ak;
            As[am][ak] = (gm < M && gk < K) ? tf32(Ap[(size_t)gm*lda + gk] * Sp[gk]) : 0u;
        }
        #pragma unroll
        for (int i = 0; i < 4; i++) {
            int idx = tid + (i << 8);
            int bk = idx >> 6, bn = idx & 63;
            int gk = kt + bk, gn = n0 + bn;
            Bs[bk][bn] = (gk < K && gn < H2) ? tf32(Bp[(size_t)gk*H2 + gn]) : 0u;
        }
        __syncthreads();
        #pragma unroll
        for (int k8 = 0; k8 < 16; k8 += 8) {
            unsigned af[2][4], bf[4][2];
            #pragma unroll
            for (int mt = 0; mt < 2; mt++) {
                int R = wm + mt*16;
                af[mt][0] = As[R+g][k8+c];
                af[mt][1] = As[R+g+8][k8+c];
                af[mt][2] = As[R+g][k8+c+4];
                af[mt][3] = As[R+g+8][k8+c+4];
            }
            #pragma unroll
            for (int nt = 0; nt < 4; nt++) {
                int Nb = wn + nt*8;
                bf[nt][0] = Bs[k8+c][Nb+g];
                bf[nt][1] = Bs[k8+c+4][Nb+g];
            }
            #pragma unroll
            for (int mt = 0; mt < 2; mt++)
                #pragma unroll
                for (int nt = 0; nt < 4; nt++)
                    mma8(acc[mt][nt], af[mt], bf[nt]);
        }
        __syncthreads();
    }

    #pragma unroll
    for (int mt = 0; mt < 2; mt++)
        #pragma unroll
        for (int nt = 0; nt < 4; nt++)
            #pragma unroll
            for (int r = 0; r < 4; r++) {
                int row = m0 + wm + mt*16 + g + ((r >> 1) << 3);
                int col = n0 + wn + nt*8 + 2*c + (r & 1);
                if (col >= H2 || row >= M) continue;
                float v = acc[mt][nt][r];
                if (mode == 0) {
                    if (row < H) { g_W0x[row*H2 + col] = v; continue; }
                    int k = row - H;
                    int n = (col < H) ? col : (896 + col - H);
                    g_Wt[0][(size_t)n*896 + k] = __float2bfloat16(v);
                } else {
                    int n = (col < H) ? col : (896 + col - H);
                    g_Wt[z+1][(size_t)n*896 + row] = __float2bfloat16(v);
                }
            }
}

// ---- tf32 XW precompute ----
__global__ void __launch_bounds__(256) xw_mma(const float* __restrict__ X)
{
    __shared__ unsigned As[128][17];
    __shared__ unsigned Bs[16][65];

    int tid = threadIdx.x;
    int w = tid >> 5, lane = tid & 31;
    int g = lane >> 2, c = lane & 3;
    int wm = (w & 3) * 32, wn = (w >> 2) * 32;
    int m0 = blockIdx.y << 7, n0 = blockIdx.x << 6;

    float acc[2][4][4];
    #pragma unroll
    for (int i = 0; i < 2; i++)
        #pragma unroll
        for (int j = 0; j < 4; j++)
            #pragma unroll
            for (int r = 0; r < 4; r++) acc[i][j][r] = 0.f;

    for (int kt = 0; kt < H; kt += 16) {
        #pragma unroll
        for (int i = 0; i < 8; i++) {
            int idx = tid + (i << 8);
            int am = idx >> 4, ak = idx & 15;
            int gk = kt + ak;
            As[am][ak] = (gk < H) ? tf32(X[(size_t)(m0+am)*H + gk]) : 0u;
        }
        #pragma unroll
        for (int i = 0; i < 4; i++) {
            int idx = tid + (i << 8);
            int bk = idx >> 6, bn = idx & 63;
            int gk = kt + bk, gn = n0 + bn;
            Bs[bk][bn] = (gk < H && gn < H2) ? tf32(g_W0x[(size_t)gk*H2 + gn]) : 0u;
        }
        __syncthreads();
        #pragma unroll
        for (int k8 = 0; k8 < 16; k8 += 8) {
            unsigned af[2][4], bf[4][2];
            #pragma unroll
            for (int mt = 0; mt < 2; mt++) {
                int R = wm + mt*16;
                af[mt][0] = As[R+g][k8+c];
                af[mt][1] = As[R+g+8][k8+c];
                af[mt][2] = As[R+g][k8+c+4];
                af[mt][3] = As[R+g+8][k8+c+4];
            }
            #pragma unroll
            for (int nt = 0; nt < 4; nt++) {
                int Nb = wn + nt*8;
                bf[nt][0] = Bs[k8+c][Nb+g];
                bf[nt][1] = Bs[k8+c+4][Nb+g];
            }
            #pragma unroll
            for (int mt = 0; mt < 2; mt++)
                #pragma unroll
                for (int nt = 0; nt < 4; nt++)
                    mma8(acc[mt][nt], af[mt], bf[nt]);
        }
        __syncthreads();
    }

    #pragma unroll
    for (int mt = 0; mt < 2; mt++)
        #pragma unroll
        for (int nt = 0; nt < 4; nt++)
            #pragma unroll
            for (int r = 0; r < 4; r++) {
                int row = m0 + wm + mt*16 + g + ((r >> 1) << 3);
                int col = n0 + wn + nt*8 + 2*c + (r & 1);
                if (col < H2) g_XW[(size_t)row*H2 + col] = acc[mt][nt][r];
            }
}

// ---- hierarchical device-wide barrier (startup only) ----
__device__ __forceinline__ void gsync(unsigned NB) {
    __syncthreads();
    if (threadIdx.x == 0) {
        __threadfence();
        unsigned my = g_gen;
        unsigned grp = blockIdx.x & 7;
        unsigned cnt = (NB - grp + 7) >> 3;
        if (atomicAdd(&g_cnt8[grp*32], 1u) == cnt - 1) {
            g_cnt8[grp*32] = 0;
            __threadfence();
            if (atomicAdd(&g_master, 1u) == 7) {
                g_master = 0;
                __threadfence();
                g_gen = my + 1;
            }
        }
        while (g_gen == my) __nanosleep(32);
        __threadfence();
    }
    __syncthreads();
}

// ---- dependency wait: thread0 spins, then block syncs ----
__device__ __forceinline__ void wait_ge(const unsigned* cnt, unsigned target) {
    if (threadIdx.x == 0) {
        while (*(volatile const unsigned*)cnt < target) __nanosleep(64);
        __threadfence();
    }
    __syncthreads();
}

// ---- bf16 64x64 (c&h) tile, 4-stage pipeline (R9 engine, unchanged) ----
__device__ __forceinline__ void tile_loads(
    unsigned (*As)[64][20], unsigned (*Bs)[2][64][20],
    const __nv_bfloat16* Ab, const __nv_bfloat16* Wt,
    int b, int m0, int n0, int kt, int tid)
{
    {
        int row = tid >> 2, q = tid & 3;
        cp16(&As[b][row][q*4], Ab + (size_t)(m0+row)*SP + kt + q*8);
    }
    #pragma unroll
    for (int i = 0; i < 2; i++) {
        int idx = tid + (i << 8);
        int mat = idx >> 8, rem = idx & 255;
        int row = rem >> 2, q = rem & 3;
        cp16(&Bs[b][mat][row][q*4],
             Wt + (size_t)(n0 + row + mat*896)*896 + kt + q*8);
    }
    asm volatile("cp.async.commit_group;");
}

__device__ __forceinline__ void frag_loads(
    unsigned (*As)[64][20], unsigned (*Bs)[2][64][20],
    unsigned (&af)[2][4], unsigned (&bf)[2][2][2],
    int buf, int kg, int wm, int wn, int g, int c)
{
    int kc = kg*8 + c;
    #pragma unroll
    for (int mt = 0; mt < 2; mt++) {
        int R = wm + mt*16;
        af[mt][0] = As[buf][R+g][kc];
        af[mt][1] = As[buf][R+g+8][kc];
        af[mt][2] = As[buf][R+g][kc+4];
        af[mt][3] = As[buf][R+g+8][kc+4];
    }
    #pragma unroll
    for (int mat = 0; mat < 2; mat++)
        #pragma unroll
        for (int nt = 0; nt < 2; nt++) {
            int Nb = wn + nt*8 + g;
            bf[mat][nt][0] = Bs[buf][mat][Nb][kc];
            bf[mat][nt][1] = Bs[buf][mat][Nb][kc+4];
        }
}

__device__ __forceinline__ void do_tile(
    unsigned (*As)[64][20], unsigned (*Bs)[2][64][20],
    const __nv_bfloat16* __restrict__ Ab, const float* __restrict__ Spf,
    const __nv_bfloat16* __restrict__ Wt, float* __restrict__ Of,
    __nv_bfloat16* __restrict__ Ob, const float* __restrict__ bias,
    int act, int m0, int n0)
{
    int tid = threadIdx.x;
    int w = tid >> 5, lane = tid & 31;
    int g = lane >> 2, c = lane & 3;
    int wm = (w & 1) * 32, wn = (w >> 1) * 16;

    float acc[2][2][2][4];
    #pragma unroll
    for (int i = 0; i < 2; i++)
        #pragma unroll
        for (int j = 0; j < 2; j++)
            #pragma unroll
            for (int k = 0; k < 2; k++)
                #pragma unroll
                for (int r = 0; r < 4; r++) acc[i][j][k][r] = 0.f;

    #pragma unroll
    for (int s = 0; s < NSTG-1; s++)
        tile_loads(As, Bs, Ab, Wt, s, m0, n0, s*32, tid);

    for (int it = 0; it < NIT; it++) {
        int buf = it & (NSTG-1);
        asm volatile("cp.async.wait_group %0;" :: "n"(NSTG-2));
        __syncthreads();
        if (it + NSTG-1 < NIT)
            tile_loads(As, Bs, Ab, Wt, (it+NSTG-1) & (NSTG-1),
                       m0, n0, (it+NSTG-1)*32, tid);
        else
            asm volatile("cp.async.commit_group;");

        unsigned af[2][2][4], bf[2][2][2][2];
        frag_loads(As, Bs, af[0], bf[0], buf, 0, wm, wn, g, c);
        #pragma unroll
        for (int kg = 0; kg < 2; kg++) {
            int cur = kg & 1;
            if (kg < 1)
                frag_loads(As, Bs, af[cur^1], bf[cur^1], buf, kg+1, wm, wn, g, c);
            #pragma unroll
            for (int mat = 0; mat < 2; mat++)
                #pragma unroll
                for (int mt = 0; mt < 2; mt++)
                    #pragma unroll
                    for (int nt = 0; nt < 2; nt++)
                        mma16(acc[mat][mt][nt], af[cur][mt], bf[cur][mat][nt]);
        }
    }

    #pragma unroll
    for (int mt = 0; mt < 2; mt++)
        #pragma unroll
        for (int nt = 0; nt < 2; nt++)
            #pragma unroll
            for (int r = 0; r < 4; r++) {
                int row = m0 + wm + mt*16 + g + ((r >> 1) << 3);
                int col = n0 + wn + nt*8 + 2*c + (r & 1);
                if (col < H) {
                    float cv = acc[0][mt][nt][r];
                    float hv = acc[1][mt][nt][r];
                    if (bias) {
                        cv += bias[(size_t)row*H2 + col];
                        hv += bias[(size_t)row*H2 + H + col];
                    }
                    float sp = Spf[(size_t)row*SP + col];
                    float o = sp + sigf(cv) * (apply_act(hv, act) - sp);
                    Of[(size_t)row*SP + col] = o;
                    Ob[(size_t)row*SP + col] = __float2bfloat16(o);
                }
            }
}

// ---- persistent recurrence: dataflow-scheduled job stream ----
__global__ void __launch_bounds__(256) rnn_persist(
    const float* __restrict__ h0, float* __restrict__ out)
{
    extern __shared__ unsigned dsm[];
    unsigned (*As)[64][20]    = (unsigned(*)[64][20])dsm;
    unsigned (*Bs)[2][64][20] = (unsigned(*)[2][64][20])(dsm + NSTG*64*20);
    __shared__ unsigned s_job;

    const unsigned NB = gridDim.x;
    const int tid = threadIdx.x;

    // job-ordered tables: job gi 0..8 -> state id
    const int jq_s[9]   = {0,1,2,3,4,5,7,6,8};     // stream order by level
    const int st_a[9]   = {-1,0,1,1,1,2,3,5,5};    // pred by state id
    const int st_w[9]   = {-1,0,1,2,3,4,6,5,7};
    const int st_act[9] = {ACT_TANH,ACT_SIG,ACT_RELU,ACT_RELU,ACT_ID,
                           ACT_TANH,ACT_TANH,ACT_SIG,ACT_RELU};

    // reset counters (persistent device globals across graph replays)
    if (blockIdx.x == 0 && tid == 0) {
        g_ticket = 0;
        for (int s = 0; s < 9; s++)
            for (int m = 0; m < 4; m++) g_done[s][m] = 0;
        for (int m = 0; m < 4; m++) g_mdone[m] = 0;
    }
    for (int i = blockIdx.x*256 + tid; i < BH; i += NB*256) {
        int pi = (i/H)*SP + (i%H);
        float v = h0[i];
        g_Hprev[pi] = v;
        g_Hb[pi] = __float2bfloat16(v);
    }
    gsync(NB);

    for (;;) {
        __syncthreads();
        if (tid == 0) s_job = atomicAdd(&g_ticket, 1u);
        __syncthreads();
        unsigned j = s_job;
        if (j >= (unsigned)TT * JPS) break;
        int t   = j / JPS;
        int idx = j % JPS;

        if (idx < 504) {                       // GEMM tile
            int gi = idx / 56;                 // job-order GEMM index 0..8
            int r  = idx % 56;
            int si = jq_s[gi];                 // state id
            int m0 = (r / 14) * 64;
            int n0 = (r % 14) * 64;
            int mblk = m0 >> 6;
            int pred = st_a[si];

            if (pred < 0) wait_ge(&g_mdone[mblk], (unsigned)t);
            else          wait_ge(&g_done[pred][mblk], 14u*(t+1));

            const __nv_bfloat16* Ab = (pred < 0) ? g_Hb : g_Sb[pred];
            const float* Spf = (pred < 0) ? g_Hprev : g_S[pred];
            const __nv_bfloat16* Wt = g_Wt[st_w[si] + 1];
            const float* bias = (pred < 0) ? (g_XW + (size_t)t*BB*H2) : nullptr;
            do_tile(As, Bs, Ab, Spf, Wt, g_S[si], g_Sb[si],
                    bias, st_act[si], m0, n0);

            __syncthreads();
            if (tid == 0) {
                __threadfence();
                atomicAdd(&g_done[si][mblk], 1u);
            }
        } else {                               // mean job
            int mblk = idx - 504;
            if (tid == 0) {
                unsigned tgt = 14u*(t+1);
                #pragma unroll
                for (int s = 1; s <= 8; s++)
                    while (*(volatile unsigned*)&g_done[s][mblk] < tgt) __nanosleep(64);
                __threadfence();
            }
            __syncthreads();

            float* od = out + (size_t)t*BH;
            int base = mblk*64;
            for (int e = tid; e < 64*H; e += 256) {
                int row = base + e / H, col = e % H;
                int pi = row*SP + col;
                float s = g_S[1][pi] + g_S[2][pi] + g_S[3][pi] + g_S[4][pi]
                        + g_S[5][pi] + g_S[6][pi] + g_S[7][pi] + g_S[8][pi];
                s *= 0.125f;
                od[(size_t)row*H + col] = s;
                g_Hprev[pi] = s;
                g_Hb[pi] = __float2bfloat16(s);
                if (t == TT-1) out[(size_t)TT*BH + (size_t)row*H + col] = s;
            }
            __syncthreads();
            if (tid == 0) {
                __threadfence();
                atomicAdd(&g_mdone[mblk], 1u);
            }
        }
    }
}

extern "C" void kernel_launch(void* const* d_in, const int* in_sizes, int n_in,
                              void* d_out, int out_size) {
    const float* X   = (const float*)d_in[0];
    const float* h0  = (const float*)d_in[1];
    const float* W0U = (const float*)d_in[2];
    const float* W0s = (const float*)d_in[3];
    const float* W0V = (const float*)d_in[4];
    const float* WsU = (const float*)d_in[5];
    const float* Wss = (const float*)d_in[6];
    const float* WsV = (const float*)d_in[7];
    float* out = (float*)d_out;

    const int smem_bytes = (NSTG*64*20 + NSTG*2*64*20) * 4;   // 61440
    static int attr_done = 0;
    if (!attr_done) {
        cudaFuncSetAttribute(rnn_persist,
            cudaFuncAttributeMaxDynamicSharedMemorySize, smem_bytes);
        attr_done = 1;
    }

    fuse_mma<<<dim3(27,14,1), 256>>>(0, W0U, W0s, W0V);
    fuse_mma<<<dim3(27,7,8),  256>>>(1, WsU, Wss, WsV);
    xw_mma<<<dim3(27,256,1), 256>>>(X);
    rnn_persist<<<148, 256, smem_bytes>>>(h0, out);
}

// round 13
// speedup vs baseline: 1.5510x; 1.5510x over previous
#include <cuda_runtime.h>
#include <cuda_bf16.h>
#include <math.h>

#define H    850
#define H2   1700
#define BB   256
#define TT   128
#define BH   (BB*H)
#define SP   896
#define NIT  28
#define NSTG 4
#define NBLK 296

__device__ float g_W0x[H*H2];
__device__ __nv_bfloat16 g_Wt[9][1792*896];   // fused weights, bf16, [n][k]
__device__ float g_XW[(size_t)TT*BB*H2];
__device__ float g_S[9][BB*SP];
__device__ __nv_bfloat16 g_Sb[9][BB*SP];
__device__ float g_Hprev[BB*SP];
__device__ __nv_bfloat16 g_Hb[BB*SP];

__device__ unsigned g_cnt8[8*32];
__device__ unsigned g_master;
__device__ volatile unsigned g_gen;

__device__ __forceinline__ unsigned tf32(float x) {
    unsigned r; asm("cvt.rna.tf32.f32 %0, %1;" : "=r"(r) : "f"(x)); return r;
}
__device__ __forceinline__ void mma8(float* d, const unsigned* a, const unsigned* b) {
    asm("mma.sync.aligned.m16n8k8.row.col.f32.tf32.tf32.f32 "
        "{%0,%1,%2,%3}, {%4,%5,%6,%7}, {%8,%9}, {%0,%1,%2,%3};"
        : "+f"(d[0]), "+f"(d[1]), "+f"(d[2]), "+f"(d[3])
        : "r"(a[0]), "r"(a[1]), "r"(a[2]), "r"(a[3]), "r"(b[0]), "r"(b[1]));
}
__device__ __forceinline__ void mma16(float* d, const unsigned* a, const unsigned* b) {
    asm("mma.sync.aligned.m16n8k16.row.col.f32.bf16.bf16.f32 "
        "{%0,%1,%2,%3}, {%4,%5,%6,%7}, {%8,%9}, {%0,%1,%2,%3};"
        : "+f"(d[0]), "+f"(d[1]), "+f"(d[2]), "+f"(d[3])
        : "r"(a[0]), "r"(a[1]), "r"(a[2]), "r"(a[3]), "r"(b[0]), "r"(b[1]));
}
__device__ __forceinline__ void cp16(void* dst, const void* src) {
    unsigned u = (unsigned)__cvta_generic_to_shared(dst);
    asm volatile("cp.async.cg.shared.global [%0], [%1], 16;" :: "r"(u), "l"(src));
}

#define ACT_TANH 0
#define ACT_RELU 1
#define ACT_SIG  2
#define ACT_ID   3
__device__ __forceinline__ float apply_act(float x, int a) {
    switch (a) {
        case ACT_TANH: return tanhf(x);
        case ACT_RELU: return fmaxf(x, 0.f);
        case ACT_SIG:  return 1.f / (1.f + expf(-x));
        default:       return x;
    }
}
__device__ __forceinline__ float sigf(float x) { return 1.f / (1.f + expf(-x)); }

// ---- tf32 weight fusion; writes g_W0x (fp32) and g_Wt (bf16 [n][k]) ----
__global__ void __launch_bounds__(256) fuse_mma(
    int mode, const float* __restrict__ A, const float* __restrict__ Sig,
    const float* __restrict__ Bx)
{
    __shared__ unsigned As[128][17];
    __shared__ unsigned Bs[16][65];

    int z = blockIdx.z;
    int M = mode ? H : H2;
    int K = M, lda = M;
    const float* Ap = A;
    const float* Sp = Sig;
    const float* Bp = Bx;
    if (mode == 1) { Ap = A + (size_t)z*H*H; Sp = Sig + z*H; Bp = Bx + (size_t)z*H2*H2; }

    int tid = threadIdx.x;
    int w = tid >> 5, lane = tid & 31;
    int g = lane >> 2, c = lane & 3;
    int wm = (w & 3) * 32, wn = (w >> 2) * 32;
    int m0 = blockIdx.y << 7, n0 = blockIdx.x << 6;

    float acc[2][4][4];
    #pragma unroll
    for (int i = 0; i < 2; i++)
        #pragma unroll
        for (int j = 0; j < 4; j++)
            #pragma unroll
            for (int r = 0; r < 4; r++) acc[i][j][r] = 0.f;

    for (int kt = 0; kt < K; kt += 16) {
        #pragma unroll
        for (int i = 0; i < 8; i++) {
            int idx = tid + (i << 8);
            int am = idx >> 4, ak = idx & 15;
            int gm = m0 + am, gk = kt + ak;
            As[am][ak] = (gm < M && gk < K) ? tf32(Ap[(size_t)gm*lda + gk] * Sp[gk]) : 0u;
        }
        #pragma unroll
        for (int i = 0; i < 4; i++) {
            int idx = tid + (i << 8);
            int bk = idx >> 6, bn = idx & 63;
            int gk = kt + bk, gn = n0 + bn;
            Bs[bk][bn] = (gk < K && gn < H2) ? tf32(Bp[(size_t)gk*H2 + gn]) : 0u;
        }
        __syncthreads();
        #pragma unroll
        for (int k8 = 0; k8 < 16; k8 += 8) {
            unsigned af[2][4], bf[4][2];
            #pragma unroll
            for (int mt = 0; mt < 2; mt++) {
                int R = wm + mt*16;
                af[mt][0] = As[R+g][k8+c];
                af[mt][1] = As[R+g+8][k8+c];
                af[mt][2] = As[R+g][k8+c+4];
                af[mt][3] = As[R+g+8][k8+c+4];
            }
            #pragma unroll
            for (int nt = 0; nt < 4; nt++) {
                int Nb = wn + nt*8;
                bf[nt][0] = Bs[k8+c][Nb+g];
                bf[nt][1] = Bs[k8+c+4][Nb+g];
            }
            #pragma unroll
            for (int mt = 0; mt < 2; mt++)
                #pragma unroll
                for (int nt = 0; nt < 4; nt++)
                    mma8(acc[mt][nt], af[mt], bf[nt]);
        }
        __syncthreads();
    }

    #pragma unroll
    for (int mt = 0; mt < 2; mt++)
        #pragma unroll
        for (int nt = 0; nt < 4; nt++)
            #pragma unroll
            for (int r = 0; r < 4; r++) {
                int row = m0 + wm + mt*16 + g + ((r >> 1) << 3);
                int col = n0 + wn + nt*8 + 2*c + (r & 1);
                if (col >= H2 || row >= M) continue;
                float v = acc[mt][nt][r];
                if (mode == 0) {
                    if (row < H) { g_W0x[row*H2 + col] = v; continue; }
                    int k = row - H;
                    int n = (col < H) ? col : (896 + col - H);
                    g_Wt[0][(size_t)n*896 + k] = __float2bfloat16(v);
                } else {
                    int n = (col < H) ? col : (896 + col - H);
                    g_Wt[z+1][(size_t)n*896 + row] = __float2bfloat16(v);
                }
            }
}

// ---- tf32 XW precompute ----
__global__ void __launch_bounds__(256) xw_mma(const float* __restrict__ X)
{
    __shared__ unsigned As[128][17];
    __shared__ unsigned Bs[16][65];

    int tid = threadIdx.x;
    int w = tid >> 5, lane = tid & 31;
    int g = lane >> 2, c = lane & 3;
    int wm = (w & 3) * 32, wn = (w >> 2) * 32;
    int m0 = blockIdx.y << 7, n0 = blockIdx.x << 6;

    float acc[2][4][4];
    #pragma unroll
    for (int i = 0; i < 2; i++)
        #pragma unroll
        for (int j = 0; j < 4; j++)
            #pragma unroll
            for (int r = 0; r < 4; r++) acc[i][j][r] = 0.f;

    for (int kt = 0; kt < H; kt += 16) {
        #pragma unroll
        for (int i = 0; i < 8; i++) {
            int idx = tid + (i << 8);
            int am = idx >> 4, ak = idx & 15;
            int gk = kt + ak;
            As[am][ak] = (gk < H) ? tf32(X[(size_t)(m0+am)*H + gk]) : 0u;
        }
        #pragma unroll
        for (int i = 0; i < 4; i++) {
            int idx = tid + (i << 8);
            int bk = idx >> 6, bn = idx & 63;
            int gk = kt + bk, gn = n0 + bn;
            Bs[bk][bn] = (gk < H && gn < H2) ? tf32(g_W0x[(size_t)gk*H2 + gn]) : 0u;
        }
        __syncthreads();
        #pragma unroll
        for (int k8 = 0; k8 < 16; k8 += 8) {
            unsigned af[2][4], bf[4][2];
            #pragma unroll
            for (int mt = 0; mt < 2; mt++) {
                int R = wm + mt*16;
                af[mt][0] = As[R+g][k8+c];
                af[mt][1] = As[R+g+8][k8+c];
                af[mt][2] = As[R+g][k8+c+4];
                af[mt][3] = As[R+g+8][k8+c+4];
            }
            #pragma unroll
            for (int nt = 0; nt < 4; nt++) {
                int Nb = wn + nt*8;
                bf[nt][0] = Bs[k8+c][Nb+g];
                bf[nt][1] = Bs[k8+c+4][Nb+g];
            }
            #pragma unroll
            for (int mt = 0; mt < 2; mt++)
                #pragma unroll
                for (int nt = 0; nt < 4; nt++)
                    mma8(acc[mt][nt], af[mt], bf[nt]);
        }
        __syncthreads();
    }

    #pragma unroll
    for (int mt = 0; mt < 2; mt++)
        #pragma unroll
        for (int nt = 0; nt < 4; nt++)
            #pragma unroll
            for (int r = 0; r < 4; r++) {
                int row = m0 + wm + mt*16 + g + ((r >> 1) << 3);
                int col = n0 + wn + nt*8 + 2*c + (r & 1);
                if (col < H2) g_XW[(size_t)row*H2 + col] = acc[mt][nt][r];
            }
}

// ---- hierarchical device-wide barrier ----
__device__ __forceinline__ void gsync(unsigned NB) {
    __syncthreads();
    if (threadIdx.x == 0) {
        __threadfence();
        unsigned my = g_gen;
        unsigned grp = blockIdx.x & 7;
        unsigned cnt = (NB - grp + 7) >> 3;
        if (atomicAdd(&g_cnt8[grp*32], 1u) == cnt - 1) {
            g_cnt8[grp*32] = 0;
            __threadfence();
            if (atomicAdd(&g_master, 1u) == 7) {
                g_master = 0;
                __threadfence();
                g_gen = my + 1;
            }
        }
        while (g_gen == my) __nanosleep(32);
        __threadfence();
    }
    __syncthreads();
}

// ---- bf16 64x64 (c&h) tile, 4-stage pipeline (R9 engine) ----
__device__ __forceinline__ void tile_loads(
    unsigned (*As)[64][20], unsigned (*Bs)[2][64][20],
    const __nv_bfloat16* Ab, const __nv_bfloat16* Wt,
    int b, int m0, int n0, int kt, int tid)
{
    {
        int row = tid >> 2, q = tid & 3;
        cp16(&As[b][row][q*4], Ab + (size_t)(m0+row)*SP + kt + q*8);
    }
    #pragma unroll
    for (int i = 0; i < 2; i++) {
        int idx = tid + (i << 8);
        int mat = idx >> 8, rem = idx & 255;
        int row = rem >> 2, q = rem & 3;
        cp16(&Bs[b][mat][row][q*4],
             Wt + (size_t)(n0 + row + mat*896)*896 + kt + q*8);
    }
    asm volatile("cp.async.commit_group;");
}

__device__ __forceinline__ void frag_loads(
    unsigned (*As)[64][20], unsigned (*Bs)[2][64][20],
    unsigned (&af)[2][4], unsigned (&bf)[2][2][2],
    int buf, int kg, int wm, int wn, int g, int c)
{
    int kc = kg*8 + c;
    #pragma unroll
    for (int mt = 0; mt < 2; mt++) {
        int R = wm + mt*16;
        af[mt][0] = As[buf][R+g][kc];
        af[mt][1] = As[buf][R+g+8][kc];
        af[mt][2] = As[buf][R+g][kc+4];
        af[mt][3] = As[buf][R+g+8][kc+4];
    }
    #pragma unroll
    for (int mat = 0; mat < 2; mat++)
        #pragma unroll
        for (int nt = 0; nt < 2; nt++) {
            int Nb = wn + nt*8 + g;
            bf[mat][nt][0] = Bs[buf][mat][Nb][kc];
            bf[mat][nt][1] = Bs[buf][mat][Nb][kc+4];
        }
}

__device__ __forceinline__ void do_tile(
    unsigned (*As)[64][20], unsigned (*Bs)[2][64][20],
    const __nv_bfloat16* __restrict__ Ab, const float* __restrict__ Spf,
    const __nv_bfloat16* __restrict__ Wt, float* __restrict__ Of,
    __nv_bfloat16* __restrict__ Ob, const float* __restrict__ bias,
    int act, int m0, int n0)
{
    int tid = threadIdx.x;
    int w = tid >> 5, lane = tid & 31;
    int g = lane >> 2, c = lane & 3;
    int wm = (w & 1) * 32, wn = (w >> 1) * 16;

    float acc[2][2][2][4];
    #pragma unroll
    for (int i = 0; i < 2; i++)
        #pragma unroll
        for (int j = 0; j < 2; j++)
            #pragma unroll
            for (int k = 0; k < 2; k++)
                #pragma unroll
                for (int r = 0; r < 4; r++) acc[i][j][k][r] = 0.f;

    #pragma unroll
    for (int s = 0; s < NSTG-1; s++)
        tile_loads(As, Bs, Ab, Wt, s, m0, n0, s*32, tid);

    for (int it = 0; it < NIT; it++) {
        int buf = it & (NSTG-1);
        asm volatile("cp.async.wait_group %0;" :: "n"(NSTG-2));
        __syncthreads();
        if (it + NSTG-1 < NIT)
            tile_loads(As, Bs, Ab, Wt, (it+NSTG-1) & (NSTG-1),
                       m0, n0, (it+NSTG-1)*32, tid);
        else
            asm volatile("cp.async.commit_group;");

        unsigned af[2][2][4], bf[2][2][2][2];
        frag_loads(As, Bs, af[0], bf[0], buf, 0, wm, wn, g, c);
        #pragma unroll
        for (int kg = 0; kg < 2; kg++) {
            int cur = kg & 1;
            if (kg < 1)
                frag_loads(As, Bs, af[cur^1], bf[cur^1], buf, kg+1, wm, wn, g, c);
            #pragma unroll
            for (int mat = 0; mat < 2; mat++)
                #pragma unroll
                for (int mt = 0; mt < 2; mt++)
                    #pragma unroll
                    for (int nt = 0; nt < 2; nt++)
                        mma16(acc[mat][mt][nt], af[cur][mt], bf[cur][mat][nt]);
        }
    }

    #pragma unroll
    for (int mt = 0; mt < 2; mt++)
        #pragma unroll
        for (int nt = 0; nt < 2; nt++)
            #pragma unroll
            for (int r = 0; r < 4; r++) {
                int row = m0 + wm + mt*16 + g + ((r >> 1) << 3);
                int col = n0 + wn + nt*8 + 2*c + (r & 1);
                if (col < H) {
                    float cv = acc[0][mt][nt][r];
                    float hv = acc[1][mt][nt][r];
                    if (bias) {
                        cv += bias[(size_t)row*H2 + col];
                        hv += bias[(size_t)row*H2 + H + col];
                    }
                    float sp = Spf[(size_t)row*SP + col];
                    float o = sp + sigf(cv) * (apply_act(hv, act) - sp);
                    Of[(size_t)row*SP + col] = o;
                    Ob[(size_t)row*SP + col] = __float2bfloat16(o);
                }
            }
}

// ---- persistent whole-recurrence kernel, 2 CTAs/SM ----
__global__ void __launch_bounds__(256) rnn_persist(
    const float* __restrict__ h0, float* __restrict__ out)
{
    extern __shared__ unsigned dsm[];
    unsigned (*As)[64][20]    = (unsigned(*)[64][20])dsm;
    unsigned (*Bs)[2][64][20] = (unsigned(*)[2][64][20])(dsm + NSTG*64*20);

    const unsigned NB = gridDim.x;
    const int tid = threadIdx.x;

    const int l_start[5] = {0,1,2,5,7};
    const int l_cnt[5]   = {1,1,3,2,2};
    const int st_a[9]   = {-1,0,1,1,1,2,3,5,5};
    const int st_w[9]   = {-1,0,1,2,3,4,6,5,7};
    const int st_o[9]   = {0,1,2,3,4,5,7,6,8};
    const int st_act[9] = {ACT_TANH,ACT_SIG,ACT_RELU,ACT_RELU,ACT_ID,
                           ACT_TANH,ACT_TANH,ACT_SIG,ACT_RELU};

    for (int i = blockIdx.x*256 + tid; i < BH; i += NB*256) {
        int pi = (i/H)*SP + (i%H);
        float v = h0[i];
        g_Hprev[pi] = v;
        g_Hb[pi] = __float2bfloat16(v);
    }
    gsync(NB);

    for (int t = 0; t < TT; t++) {
        for (int lvl = 0; lvl < 5; lvl++) {
            int base = l_start[lvl];
            int njobs = l_cnt[lvl] * 56;
            for (int job = blockIdx.x; job < njobs; job += NB) {
                int si = base + job / 56;
                int r  = job % 56;
                int m0 = (r / 14) * 64;
                int n0 = (r % 14) * 64;
                const __nv_bfloat16* Ab = (st_a[si] < 0) ? g_Hb : g_Sb[st_a[si]];
                const float* Spf = (st_a[si] < 0) ? g_Hprev : g_S[st_a[si]];
                const __nv_bfloat16* Wt = g_Wt[st_w[si] + 1];
                const float* bias = (st_a[si] < 0) ? (g_XW + (size_t)t*BB*H2) : nullptr;
                do_tile(As, Bs, Ab, Spf, Wt, g_S[st_o[si]], g_Sb[st_o[si]],
                        bias, st_act[si], m0, n0);
            }
            gsync(NB);
        }
        float* od = out + (size_t)t*BH;
        for (int i = blockIdx.x*256 + tid; i < BH; i += NB*256) {
            int pi = (i/H)*SP + (i%H);
            float s = g_S[1][pi] + g_S[2][pi] + g_S[3][pi] + g_S[4][pi]
                    + g_S[5][pi] + g_S[6][pi] + g_S[7][pi] + g_S[8][pi];
            s *= 0.125f;
            od[i] = s;
            g_Hprev[pi] = s;
            g_Hb[pi] = __float2bfloat16(s);
            if (t == TT-1) out[(size_t)TT*BH + i] = s;
        }
        gsync(NB);
    }
}

extern "C" void kernel_launch(void* const* d_in, const int* in_sizes, int n_in,
                              void* d_out, int out_size) {
    const float* X   = (const float*)d_in[0];
    const float* h0  = (const float*)d_in[1];
    const float* W0U = (const float*)d_in[2];
    const float* W0s = (const float*)d_in[3];
    const float* W0V = (const float*)d_in[4];
    const float* WsU = (const float*)d_in[5];
    const float* Wss = (const float*)d_in[6];
    const float* WsV = (const float*)d_in[7];
    float* out = (float*)d_out;

    const int smem_bytes = (NSTG*64*20 + NSTG*2*64*20) * 4;   // 61440
    static int attr_done = 0;
    if (!attr_done) {
        cudaFuncSetAttribute(rnn_persist,
            cudaFuncAttributeMaxDynamicSharedMemorySize, smem_bytes);
        attr_done = 1;
    }

    fuse_mma<<<dim3(27,14,1), 256>>>(0, W0U, W0s, W0V);
    fuse_mma<<<dim3(27,7,8),  256>>>(1, WsU, Wss, WsV);
    xw_mma<<<dim3(27,256,1), 256>>>(X);
    rnn_persist<<<NBLK, 256, smem_bytes>>>(h0, out);
}

// round 14
// speedup vs baseline: 1.7114x; 1.1034x over previous
#include <cuda_runtime.h>
#include <cuda_bf16.h>
#include <math.h>

#define H    850
#define H2   1700
#define BB   256
#define TT   128
#define BH   (BB*H)
#define SP   896
#define NIT  28
#define NSTG 4
#define NBLK 444
#define TJ   112          // tiles per GEMM (8 m-blocks x 14 n-blocks)

__device__ float g_W0x[H*H2];
__device__ __nv_bfloat16 g_Wt[9][1792*896];   // fused weights, bf16, [n][k]
__device__ float g_XW[(size_t)TT*BB*H2];
__device__ float g_S[9][BB*SP];
__device__ __nv_bfloat16 g_Sb[9][BB*SP];
__device__ float g_Hprev[BB*SP];
__device__ __nv_bfloat16 g_Hb[BB*SP];

__device__ unsigned g_cnt8[8*32];
__device__ unsigned g_master;
__device__ volatile unsigned g_gen;

__device__ __forceinline__ unsigned tf32(float x) {
    unsigned r; asm("cvt.rna.tf32.f32 %0, %1;" : "=r"(r) : "f"(x)); return r;
}
__device__ __forceinline__ void mma8(float* d, const unsigned* a, const unsigned* b) {
    asm("mma.sync.aligned.m16n8k8.row.col.f32.tf32.tf32.f32 "
        "{%0,%1,%2,%3}, {%4,%5,%6,%7}, {%8,%9}, {%0,%1,%2,%3};"
        : "+f"(d[0]), "+f"(d[1]), "+f"(d[2]), "+f"(d[3])
        : "r"(a[0]), "r"(a[1]), "r"(a[2]), "r"(a[3]), "r"(b[0]), "r"(b[1]));
}
__device__ __forceinline__ void mma16(float* d, const unsigned* a, const unsigned* b) {
    asm("mma.sync.aligned.m16n8k16.row.col.f32.bf16.bf16.f32 "
        "{%0,%1,%2,%3}, {%4,%5,%6,%7}, {%8,%9}, {%0,%1,%2,%3};"
        : "+f"(d[0]), "+f"(d[1]), "+f"(d[2]), "+f"(d[3])
        : "r"(a[0]), "r"(a[1]), "r"(a[2]), "r"(a[3]), "r"(b[0]), "r"(b[1]));
}
__device__ __forceinline__ void cp16(void* dst, const void* src) {
    unsigned u = (unsigned)__cvta_generic_to_shared(dst);
    asm volatile("cp.async.cg.shared.global [%0], [%1], 16;" :: "r"(u), "l"(src));
}

#define ACT_TANH 0
#define ACT_RELU 1
#define ACT_SIG  2
#define ACT_ID   3
__device__ __forceinline__ float apply_act(float x, int a) {
    switch (a) {
        case ACT_TANH: return tanhf(x);
        case ACT_RELU: return fmaxf(x, 0.f);
        case ACT_SIG:  return 1.f / (1.f + expf(-x));
        default:       return x;
    }
}
__device__ __forceinline__ float sigf(float x) { return 1.f / (1.f + expf(-x)); }

// ---- tf32 weight fusion; writes g_W0x (fp32) and g_Wt (bf16 [n][k]) ----
__global__ void __launch_bounds__(256) fuse_mma(
    int mode, const float* __restrict__ A, const float* __restrict__ Sig,
    const float* __restrict__ Bx)
{
    __shared__ unsigned As[128][17];
    __shared__ unsigned Bs[16][65];

    int z = blockIdx.z;
    int M = mode ? H : H2;
    int K = M, lda = M;
    const float* Ap = A;
    const float* Sp = Sig;
    const float* Bp = Bx;
    if (mode == 1) { Ap = A + (size_t)z*H*H; Sp = Sig + z*H; Bp = Bx + (size_t)z*H2*H2; }

    int tid = threadIdx.x;
    int w = tid >> 5, lane = tid & 31;
    int g = lane >> 2, c = lane & 3;
    int wm = (w & 3) * 32, wn = (w >> 2) * 32;
    int m0 = blockIdx.y << 7, n0 = blockIdx.x << 6;

    float acc[2][4][4];
    #pragma unroll
    for (int i = 0; i < 2; i++)
        #pragma unroll
        for (int j = 0; j < 4; j++)
            #pragma unroll
            for (int r = 0; r < 4; r++) acc[i][j][r] = 0.f;

    for (int kt = 0; kt < K; kt += 16) {
        #pragma unroll
        for (int i = 0; i < 8; i++) {
            int idx = tid + (i << 8);
            int am = idx >> 4, ak = idx & 15;
            int gm = m0 + am, gk = kt + ak;
            As[am][ak] = (gm < M && gk < K) ? tf32(Ap[(size_t)gm*lda + gk] * Sp[gk]) : 0u;
        }
        #pragma unroll
        for (int i = 0; i < 4; i++) {
            int idx = tid + (i << 8);
            int bk = idx >> 6, bn = idx & 63;
            int gk = kt + bk, gn = n0 + bn;
            Bs[bk][bn] = (gk < K && gn < H2) ? tf32(Bp[(size_t)gk*H2 + gn]) : 0u;
        }
        __syncthreads();
        #pragma unroll
        for (int k8 = 0; k8 < 16; k8 += 8) {
            unsigned af[2][4], bf[4][2];
            #pragma unroll
            for (int mt = 0; mt < 2; mt++) {
                int R = wm + mt*16;
                af[mt][0] = As[R+g][k8+c];
                af[mt][1] = As[R+g+8][k8+c];
                af[mt][2] = As[R+g][k8+c+4];
                af[mt][3] = As[R+g+8][k8+c+4];
            }
            #pragma unroll
            for (int nt = 0; nt < 4; nt++) {
                int Nb = wn + nt*8;
                bf[nt][0] = Bs[k8+c][Nb+g];
                bf[nt][1] = Bs[k8+c+4][Nb+g];
            }
            #pragma unroll
            for (int mt = 0; mt < 2; mt++)
                #pragma unroll
                for (int nt = 0; nt < 4; nt++)
                    mma8(acc[mt][nt], af[mt], bf[nt]);
        }
        __syncthreads();
    }

    #pragma unroll
    for (int mt = 0; mt < 2; mt++)
        #pragma unroll
        for (int nt = 0; nt < 4; nt++)
            #pragma unroll
            for (int r = 0; r < 4; r++) {
                int row = m0 + wm + mt*16 + g + ((r >> 1) << 3);
                int col = n0 + wn + nt*8 + 2*c + (r & 1);
                if (col >= H2 || row >= M) continue;
                float v = acc[mt][nt][r];
                if (mode == 0) {
                    if (row < H) { g_W0x[row*H2 + col] = v; continue; }
                    int k = row - H;
                    int n = (col < H) ? col : (896 + col - H);
                    g_Wt[0][(size_t)n*896 + k] = __float2bfloat16(v);
                } else {
                    int n = (col < H) ? col : (896 + col - H);
                    g_Wt[z+1][(size_t)n*896 + row] = __float2bfloat16(v);
                }
            }
}

// ---- tf32 XW precompute ----
__global__ void __launch_bounds__(256) xw_mma(const float* __restrict__ X)
{
    __shared__ unsigned As[128][17];
    __shared__ unsigned Bs[16][65];

    int tid = threadIdx.x;
    int w = tid >> 5, lane = tid & 31;
    int g = lane >> 2, c = lane & 3;
    int wm = (w & 3) * 32, wn = (w >> 2) * 32;
    int m0 = blockIdx.y << 7, n0 = blockIdx.x << 6;

    float acc[2][4][4];
    #pragma unroll
    for (int i = 0; i < 2; i++)
        #pragma unroll
        for (int j = 0; j < 4; j++)
            #pragma unroll
            for (int r = 0; r < 4; r++) acc[i][j][r] = 0.f;

    for (int kt = 0; kt < H; kt += 16) {
        #pragma unroll
        for (int i = 0; i < 8; i++) {
            int idx = tid + (i << 8);
            int am = idx >> 4, ak = idx & 15;
            int gk = kt + ak;
            As[am][ak] = (gk < H) ? tf32(X[(size_t)(m0+am)*H + gk]) : 0u;
        }
        #pragma unroll
        for (int i = 0; i < 4; i++) {
            int idx = tid + (i << 8);
            int bk = idx >> 6, bn = idx & 63;
            int gk = kt + bk, gn = n0 + bn;
            Bs[bk][bn] = (gk < H && gn < H2) ? tf32(g_W0x[(size_t)gk*H2 + gn]) : 0u;
        }
        __syncthreads();
        #pragma unroll
        for (int k8 = 0; k8 < 16; k8 += 8) {
            unsigned af[2][4], bf[4][2];
            #pragma unroll
            for (int mt = 0; mt < 2; mt++) {
                int R = wm + mt*16;
                af[mt][0] = As[R+g][k8+c];
                af[mt][1] = As[R+g+8][k8+c];
                af[mt][2] = As[R+g][k8+c+4];
                af[mt][3] = As[R+g+8][k8+c+4];
            }
            #pragma unroll
            for (int nt = 0; nt < 4; nt++) {
                int Nb = wn + nt*8;
                bf[nt][0] = Bs[k8+c][Nb+g];
                bf[nt][1] = Bs[k8+c+4][Nb+g];
            }
            #pragma unroll
            for (int mt = 0; mt < 2; mt++)
                #pragma unroll
                for (int nt = 0; nt < 4; nt++)
                    mma8(acc[mt][nt], af[mt], bf[nt]);
        }
        __syncthreads();
    }

    #pragma unroll
    for (int mt = 0; mt < 2; mt++)
        #pragma unroll
        for (int nt = 0; nt < 4; nt++)
            #pragma unroll
            for (int r = 0; r < 4; r++) {
                int row = m0 + wm + mt*16 + g + ((r >> 1) << 3);
                int col = n0 + wn + nt*8 + 2*c + (r & 1);
                if (col < H2) g_XW[(size_t)row*H2 + col] = acc[mt][nt][r];
            }
}

// ---- hierarchical device-wide barrier ----
__device__ __forceinline__ void gsync(unsigned NB) {
    __syncthreads();
    if (threadIdx.x == 0) {
        __threadfence();
        unsigned my = g_gen;
        unsigned grp = blockIdx.x & 7;
        unsigned cnt = (NB - grp + 7) >> 3;
        if (atomicAdd(&g_cnt8[grp*32], 1u) == cnt - 1) {
            g_cnt8[grp*32] = 0;
            __threadfence();
            if (atomicAdd(&g_master, 1u) == 7) {
                g_master = 0;
                __threadfence();
                g_gen = my + 1;
            }
        }
        while (g_gen == my) __nanosleep(32);
        __threadfence();
    }
    __syncthreads();
}

// ---- bf16 32x64 (c&h) tile, 4-stage pipeline ----
// As: [NSTG][32][20] u32 (bf16x2), Bs: [NSTG][2][64][20]
__device__ __forceinline__ void tile_loads(
    unsigned (*As)[32][20], unsigned (*Bs)[2][64][20],
    const __nv_bfloat16* Ab, const __nv_bfloat16* Wt,
    int b, int m0, int n0, int kt, int tid)
{
    if (tid < 128) {
        int row = tid >> 2, q = tid & 3;
        cp16(&As[b][row][q*4], Ab + (size_t)(m0+row)*SP + kt + q*8);
    }
    #pragma unroll
    for (int i = 0; i < 2; i++) {
        int idx = tid + (i << 8);
        int mat = idx >> 8, rem = idx & 255;
        int row = rem >> 2, q = rem & 3;
        cp16(&Bs[b][mat][row][q*4],
             Wt + (size_t)(n0 + row + mat*896)*896 + kt + q*8);
    }
    asm volatile("cp.async.commit_group;");
}

__device__ __forceinline__ void frag_loads(
    unsigned (*As)[32][20], unsigned (*Bs)[2][64][20],
    unsigned (&af)[4], unsigned (&bf)[2][2][2],
    int buf, int kg, int wm, int wn, int g, int c)
{
    int kc = kg*8 + c;
    af[0] = As[buf][wm+g][kc];
    af[1] = As[buf][wm+g+8][kc];
    af[2] = As[buf][wm+g][kc+4];
    af[3] = As[buf][wm+g+8][kc+4];
    #pragma unroll
    for (int mat = 0; mat < 2; mat++)
        #pragma unroll
        for (int nt = 0; nt < 2; nt++) {
            int Nb = wn + nt*8 + g;
            bf[mat][nt][0] = Bs[buf][mat][Nb][kc];
            bf[mat][nt][1] = Bs[buf][mat][Nb][kc+4];
        }
}

__device__ __forceinline__ void do_tile(
    unsigned (*As)[32][20], unsigned (*Bs)[2][64][20],
    const __nv_bfloat16* __restrict__ Ab, const float* __restrict__ Spf,
    const __nv_bfloat16* __restrict__ Wt, float* __restrict__ Of,
    __nv_bfloat16* __restrict__ Ob, const float* __restrict__ bias,
    int act, int m0, int n0)
{
    int tid = threadIdx.x;
    int w = tid >> 5, lane = tid & 31;
    int g = lane >> 2, c = lane & 3;
    int wm = (w & 1) * 16, wn = (w >> 1) * 16;   // 2m x 4n warps over 32x64

    float acc[2][2][4];
    #pragma unroll
    for (int i = 0; i < 2; i++)
        #pragma unroll
        for (int k = 0; k < 2; k++)
            #pragma unroll
            for (int r = 0; r < 4; r++) acc[i][k][r] = 0.f;

    #pragma unroll
    for (int s = 0; s < NSTG-1; s++)
        tile_loads(As, Bs, Ab, Wt, s, m0, n0, s*32, tid);

    for (int it = 0; it < NIT; it++) {
        int buf = it & (NSTG-1);
        asm volatile("cp.async.wait_group %0;" :: "n"(NSTG-2));
        __syncthreads();
        if (it + NSTG-1 < NIT)
            tile_loads(As, Bs, Ab, Wt, (it+NSTG-1) & (NSTG-1),
                       m0, n0, (it+NSTG-1)*32, tid);
        else
            asm volatile("cp.async.commit_group;");

        unsigned af[2][4], bf[2][2][2][2];
        frag_loads(As, Bs, af[0], bf[0], buf, 0, wm, wn, g, c);
        #pragma unroll
        for (int kg = 0; kg < 2; kg++) {
            int cur = kg & 1;
            if (kg < 1)
                frag_loads(As, Bs, af[cur^1], bf[cur^1], buf, kg+1, wm, wn, g, c);
            #pragma unroll
            for (int mat = 0; mat < 2; mat++)
                #pragma unroll
                for (int nt = 0; nt < 2; nt++)
                    mma16(acc[mat][nt], af[cur], bf[cur][mat][nt]);
        }
    }

    #pragma unroll
    for (int nt = 0; nt < 2; nt++)
        #pragma unroll
        for (int r = 0; r < 4; r++) {
            int row = m0 + wm + g + ((r >> 1) << 3);
            int col = n0 + wn + nt*8 + 2*c + (r & 1);
            if (col < H) {
                float cv = acc[0][nt][r];
                float hv = acc[1][nt][r];
                if (bias) {
                    cv += bias[(size_t)row*H2 + col];
                    hv += bias[(size_t)row*H2 + H + col];
                }
                float sp = Spf[(size_t)row*SP + col];
                float o = sp + sigf(cv) * (apply_act(hv, act) - sp);
                Of[(size_t)row*SP + col] = o;
                Ob[(size_t)row*SP + col] = __float2bfloat16(o);
            }
        }
}

// ---- persistent whole-recurrence kernel, 3 CTAs/SM ----
__global__ void __launch_bounds__(256, 3) rnn_persist(
    const float* __restrict__ h0, float* __restrict__ out)
{
    extern __shared__ unsigned dsm[];
    unsigned (*As)[32][20]    = (unsigned(*)[32][20])dsm;
    unsigned (*Bs)[2][64][20] = (unsigned(*)[2][64][20])(dsm + NSTG*32*20);

    const unsigned NB = gridDim.x;
    const int tid = threadIdx.x;

    const int l_start[5] = {0,1,2,5,7};
    const int l_cnt[5]   = {1,1,3,2,2};
    const int st_a[9]   = {-1,0,1,1,1,2,3,5,5};
    const int st_w[9]   = {-1,0,1,2,3,4,6,5,7};
    const int st_o[9]   = {0,1,2,3,4,5,7,6,8};
    const int st_act[9] = {ACT_TANH,ACT_SIG,ACT_RELU,ACT_RELU,ACT_ID,
                           ACT_TANH,ACT_TANH,ACT_SIG,ACT_RELU};

    for (int i = blockIdx.x*256 + tid; i < BH; i += NB*256) {
        int pi = (i/H)*SP + (i%H);
        float v = h0[i];
        g_Hprev[pi] = v;
        g_Hb[pi] = __float2bfloat16(v);
    }
    gsync(NB);

    for (int t = 0; t < TT; t++) {
        for (int lvl = 0; lvl < 5; lvl++) {
            int base = l_start[lvl];
            int njobs = l_cnt[lvl] * TJ;
            for (int job = blockIdx.x; job < njobs; job += NB) {
                int si = base + job / TJ;
                int r  = job % TJ;
                int m0 = (r / 14) * 32;
                int n0 = (r % 14) * 64;
                const __nv_bfloat16* Ab = (st_a[si] < 0) ? g_Hb : g_Sb[st_a[si]];
                const float* Spf = (st_a[si] < 0) ? g_Hprev : g_S[st_a[si]];
                const __nv_bfloat16* Wt = g_Wt[st_w[si] + 1];
                const float* bias = (st_a[si] < 0) ? (g_XW + (size_t)t*BB*H2) : nullptr;
                do_tile(As, Bs, Ab, Spf, Wt, g_S[st_o[si]], g_Sb[st_o[si]],
                        bias, st_act[si], m0, n0);
            }
            gsync(NB);
        }
        float* od = out + (size_t)t*BH;
        for (int i = blockIdx.x*256 + tid; i < BH; i += NB*256) {
            int pi = (i/H)*SP + (i%H);
            float s = g_S[1][pi] + g_S[2][pi] + g_S[3][pi] + g_S[4][pi]
                    + g_S[5][pi] + g_S[6][pi] + g_S[7][pi] + g_S[8][pi];
            s *= 0.125f;
            od[i] = s;
            g_Hprev[pi] = s;
            g_Hb[pi] = __float2bfloat16(s);
            if (t == TT-1) out[(size_t)TT*BH + i] = s;
        }
        gsync(NB);
    }
}

extern "C" void kernel_launch(void* const* d_in, const int* in_sizes, int n_in,
                              void* d_out, int out_size) {
    const float* X   = (const float*)d_in[0];
    const float* h0  = (const float*)d_in[1];
    const float* W0U = (const float*)d_in[2];
    const float* W0s = (const float*)d_in[3];
    const float* W0V = (const float*)d_in[4];
    const float* WsU = (const float*)d_in[5];
    const float* Wss = (const float*)d_in[6];
    const float* WsV = (const float*)d_in[7];
    float* out = (float*)d_out;

    const int smem_bytes = (NSTG*32*20 + NSTG*2*64*20) * 4;   // 51200
    static int attr_done = 0;
    if (!attr_done) {
        cudaFuncSetAttribute(rnn_persist,
            cudaFuncAttributeMaxDynamicSharedMemorySize, smem_bytes);
        attr_done = 1;
    }

    fuse_mma<<<dim3(27,14,1), 256>>>(0, W0U, W0s, W0V);
    fuse_mma<<<dim3(27,7,8),  256>>>(1, WsU, Wss, WsV);
    xw_mma<<<dim3(27,256,1), 256>>>(X);
    rnn_persist<<<NBLK, 256, smem_bytes>>>(h0, out);
}

// round 15
// speedup vs baseline: 1.8456x; 1.0784x over previous
#include <cuda_runtime.h>
#include <cuda_bf16.h>
#include <math.h>

#define H    850
#define H2   1700
#define BB   256
#define TT   128
#define BH   (BB*H)
#define SP   896
#define NIT  14           // K iterations at BK=64
#define NSTG 3
#define NBLK 444
#define TJ   112          // tiles per GEMM (8 m-blocks x 14 n-blocks)

__device__ float g_W0x[H*H2];
__device__ __nv_bfloat16 g_Wt[9][1792*896];   // fused weights, bf16, [n][k]
__device__ float g_XW[(size_t)TT*BB*H2];
__device__ float g_S[9][BB*SP];
__device__ __nv_bfloat16 g_Sb[9][BB*SP];
__device__ float g_Hprev[BB*SP];
__device__ __nv_bfloat16 g_Hb[BB*SP];

__device__ unsigned g_cnt8[8*32];
__device__ unsigned g_master;
__device__ volatile unsigned g_gen;

__device__ __forceinline__ unsigned tf32(float x) {
    unsigned r; asm("cvt.rna.tf32.f32 %0, %1;" : "=r"(r) : "f"(x)); return r;
}
__device__ __forceinline__ void mma8(float* d, const unsigned* a, const unsigned* b) {
    asm("mma.sync.aligned.m16n8k8.row.col.f32.tf32.tf32.f32 "
        "{%0,%1,%2,%3}, {%4,%5,%6,%7}, {%8,%9}, {%0,%1,%2,%3};"
        : "+f"(d[0]), "+f"(d[1]), "+f"(d[2]), "+f"(d[3])
        : "r"(a[0]), "r"(a[1]), "r"(a[2]), "r"(a[3]), "r"(b[0]), "r"(b[1]));
}
__device__ __forceinline__ void mma16(float* d, const unsigned* a, const unsigned* b) {
    asm("mma.sync.aligned.m16n8k16.row.col.f32.bf16.bf16.f32 "
        "{%0,%1,%2,%3}, {%4,%5,%6,%7}, {%8,%9}, {%0,%1,%2,%3};"
        : "+f"(d[0]), "+f"(d[1]), "+f"(d[2]), "+f"(d[3])
        : "r"(a[0]), "r"(a[1]), "r"(a[2]), "r"(a[3]), "r"(b[0]), "r"(b[1]));
}
__device__ __forceinline__ void cp16(void* dst, const void* src) {
    unsigned u = (unsigned)__cvta_generic_to_shared(dst);
    asm volatile("cp.async.cg.shared.global [%0], [%1], 16;" :: "r"(u), "l"(src));
}

#define ACT_TANH 0
#define ACT_RELU 1
#define ACT_SIG  2
#define ACT_ID   3
__device__ __forceinline__ float apply_act(float x, int a) {
    switch (a) {
        case ACT_TANH: return tanhf(x);
        case ACT_RELU: return fmaxf(x, 0.f);
        case ACT_SIG:  return 1.f / (1.f + expf(-x));
        default:       return x;
    }
}
__device__ __forceinline__ float sigf(float x) { return 1.f / (1.f + expf(-x)); }

// ---- tf32 weight fusion; writes g_W0x (fp32) and g_Wt (bf16 [n][k]) ----
__global__ void __launch_bounds__(256) fuse_mma(
    int mode, const float* __restrict__ A, const float* __restrict__ Sig,
    const float* __restrict__ Bx)
{
    __shared__ unsigned As[128][17];
    __shared__ unsigned Bs[16][65];

    int z = blockIdx.z;
    int M = mode ? H : H2;
    int K = M, lda = M;
    const float* Ap = A;
    const float* Sp = Sig;
    const float* Bp = Bx;
    if (mode == 1) { Ap = A + (size_t)z*H*H; Sp = Sig + z*H; Bp = Bx + (size_t)z*H2*H2; }

    int tid = threadIdx.x;
    int w = tid >> 5, lane = tid & 31;
    int g = lane >> 2, c = lane & 3;
    int wm = (w & 3) * 32, wn = (w >> 2) * 32;
    int m0 = blockIdx.y << 7, n0 = blockIdx.x << 6;

    float acc[2][4][4];
    #pragma unroll
    for (int i = 0; i < 2; i++)
        #pragma unroll
        for (int j = 0; j < 4; j++)
            #pragma unroll
            for (int r = 0; r < 4; r++) acc[i][j][r] = 0.f;

    for (int kt = 0; kt < K; kt += 16) {
        #pragma unroll
        for (int i = 0; i < 8; i++) {
            int idx = tid + (i << 8);
            int am = idx >> 4, ak = idx & 15;
            int gm = m0 + am, gk = kt + ak;
            As[am][ak] = (gm < M && gk < K) ? tf32(Ap[(size_t)gm*lda + gk] * Sp[gk]) : 0u;
        }
        #pragma unroll
        for (int i = 0; i < 4; i++) {
            int idx = tid + (i << 8);
            int bk = idx >> 6, bn = idx & 63;
            int gk = kt + bk, gn = n0 + bn;
            Bs[bk][bn] = (gk < K && gn < H2) ? tf32(Bp[(size_t)gk*H2 + gn]) : 0u;
        }
        __syncthreads();
        #pragma unroll
        for (int k8 = 0; k8 < 16; k8 += 8) {
            unsigned af[2][4], bf[4][2];
            #pragma unroll
            for (int mt = 0; mt < 2; mt++) {
                int R = wm + mt*16;
                af[mt][0] = As[R+g][k8+c];
                af[mt][1] = As[R+g+8][k8+c];
                af[mt][2] = As[R+g][k8+c+4];
                af[mt][3] = As[R+g+8][k8+c+4];
            }
            #pragma unroll
            for (int nt = 0; nt < 4; nt++) {
                int Nb = wn + nt*8;
                bf[nt][0] = Bs[k8+c][Nb+g];
                bf[nt][1] = Bs[k8+c+4][Nb+g];
            }
            #pragma unroll
            for (int mt = 0; mt < 2; mt++)
                #pragma unroll
                for (int nt = 0; nt < 4; nt++)
                    mma8(acc[mt][nt], af[mt], bf[nt]);
        }
        __syncthreads();
    }

    #pragma unroll
    for (int mt = 0; mt < 2; mt++)
        #pragma unroll
        for (int nt = 0; nt < 4; nt++)
            #pragma unroll
            for (int r = 0; r < 4; r++) {
                int row = m0 + wm + mt*16 + g + ((r >> 1) << 3);
                int col = n0 + wn + nt*8 + 2*c + (r & 1);
                if (col >= H2 || row >= M) continue;
                float v = acc[mt][nt][r];
                if (mode == 0) {
                    if (row < H) { g_W0x[row*H2 + col] = v; continue; }
                    int k = row - H;
                    int n = (col < H) ? col : (896 + col - H);
                    g_Wt[0][(size_t)n*896 + k] = __float2bfloat16(v);
                } else {
                    int n = (col < H) ? col : (896 + col - H);
                    g_Wt[z+1][(size_t)n*896 + row] = __float2bfloat16(v);
                }
            }
}

// ---- tf32 XW precompute ----
__global__ void __launch_bounds__(256) xw_mma(const float* __restrict__ X)
{
    __shared__ unsigned As[128][17];
    __shared__ unsigned Bs[16][65];

    int tid = threadIdx.x;
    int w = tid >> 5, lane = tid & 31;
    int g = lane >> 2, c = lane & 3;
    int wm = (w & 3) * 32, wn = (w >> 2) * 32;
    int m0 = blockIdx.y << 7, n0 = blockIdx.x << 6;

    float acc[2][4][4];
    #pragma unroll
    for (int i = 0; i < 2; i++)
        #pragma unroll
        for (int j = 0; j < 4; j++)
            #pragma unroll
            for (int r = 0; r < 4; r++) acc[i][j][r] = 0.f;

    for (int kt = 0; kt < H; kt += 16) {
        #pragma unroll
        for (int i = 0; i < 8; i++) {
            int idx = tid + (i << 8);
            int am = idx >> 4, ak = idx & 15;
            int gk = kt + ak;
            As[am][ak] = (gk < H) ? tf32(X[(size_t)(m0+am)*H + gk]) : 0u;
        }
        #pragma unroll
        for (int i = 0; i < 4; i++) {
            int idx = tid + (i << 8);
            int bk = idx >> 6, bn = idx & 63;
            int gk = kt + bk, gn = n0 + bn;
            Bs[bk][bn] = (gk < H && gn < H2) ? tf32(g_W0x[(size_t)gk*H2 + gn]) : 0u;
        }
        __syncthreads();
        #pragma unroll
        for (int k8 = 0; k8 < 16; k8 += 8) {
            unsigned af[2][4], bf[4][2];
            #pragma unroll
            for (int mt = 0; mt < 2; mt++) {
                int R = wm + mt*16;
                af[mt][0] = As[R+g][k8+c];
                af[mt][1] = As[R+g+8][k8+c];
                af[mt][2] = As[R+g][k8+c+4];
                af[mt][3] = As[R+g+8][k8+c+4];
            }
            #pragma unroll
            for (int nt = 0; nt < 4; nt++) {
                int Nb = wn + nt*8;
                bf[nt][0] = Bs[k8+c][Nb+g];
                bf[nt][1] = Bs[k8+c+4][Nb+g];
            }
            #pragma unroll
            for (int mt = 0; mt < 2; mt++)
                #pragma unroll
                for (int nt = 0; nt < 4; nt++)
                    mma8(acc[mt][nt], af[mt], bf[nt]);
        }
        __syncthreads();
    }

    #pragma unroll
    for (int mt = 0; mt < 2; mt++)
        #pragma unroll
        for (int nt = 0; nt < 4; nt++)
            #pragma unroll
            for (int r = 0; r < 4; r++) {
                int row = m0 + wm + mt*16 + g + ((r >> 1) << 3);
                int col = n0 + wn + nt*8 + 2*c + (r & 1);
                if (col < H2) g_XW[(size_t)row*H2 + col] = acc[mt][nt][r];
            }
}

// ---- hierarchical device-wide barrier ----
__device__ __forceinline__ void gsync(unsigned NB) {
    __syncthreads();
    if (threadIdx.x == 0) {
        __threadfence();
        unsigned my = g_gen;
        unsigned grp = blockIdx.x & 7;
        unsigned cnt = (NB - grp + 7) >> 3;
        if (atomicAdd(&g_cnt8[grp*32], 1u) == cnt - 1) {
            g_cnt8[grp*32] = 0;
            __threadfence();
            if (atomicAdd(&g_master, 1u) == 7) {
                g_master = 0;
                __threadfence();
                g_gen = my + 1;
            }
        }
        while (g_gen == my) __nanosleep(32);
        __threadfence();
    }
    __syncthreads();
}

// ---- bf16 32x64 (c&h) tile, BK=64, 3-stage pipeline ----
// As: [NSTG][32][36] u32 (bf16x2), Bs: [NSTG][2][64][36]
__device__ __forceinline__ void tile_loads(
    unsigned (*As)[32][36], unsigned (*Bs)[2][64][36],
    const __nv_bfloat16* Ab, const __nv_bfloat16* Wt,
    int b, int m0, int n0, int kt, int tid)
{
    {
        int row = tid >> 3, q = tid & 7;           // 256 = 32 rows x 8 chunks
        cp16(&As[b][row][q*4], Ab + (size_t)(m0+row)*SP + kt + q*8);
    }
    #pragma unroll
    for (int i = 0; i < 4; i++) {
        int idx = tid + (i << 8);
        int mat = idx >> 9, rem = idx & 511;
        int row = rem >> 3, q = rem & 7;
        cp16(&Bs[b][mat][row][q*4],
             Wt + (size_t)(n0 + row + mat*896)*896 + kt + q*8);
    }
    asm volatile("cp.async.commit_group;");
}

__device__ __forceinline__ void frag_loads(
    unsigned (*As)[32][36], unsigned (*Bs)[2][64][36],
    unsigned (&af)[4], unsigned (&bf)[2][2][2],
    int buf, int kg, int wm, int wn, int g, int c)
{
    int kc = kg*8 + c;
    af[0] = As[buf][wm+g][kc];
    af[1] = As[buf][wm+g+8][kc];
    af[2] = As[buf][wm+g][kc+4];
    af[3] = As[buf][wm+g+8][kc+4];
    #pragma unroll
    for (int mat = 0; mat < 2; mat++)
        #pragma unroll
        for (int nt = 0; nt < 2; nt++) {
            int Nb = wn + nt*8 + g;
            bf[mat][nt][0] = Bs[buf][mat][Nb][kc];
            bf[mat][nt][1] = Bs[buf][mat][Nb][kc+4];
        }
}

__device__ __forceinline__ void do_tile(
    unsigned (*As)[32][36], unsigned (*Bs)[2][64][36],
    const __nv_bfloat16* __restrict__ Ab, const float* __restrict__ Spf,
    const __nv_bfloat16* __restrict__ Wt, float* __restrict__ Of,
    __nv_bfloat16* __restrict__ Ob, const float* __restrict__ bias,
    int act, int m0, int n0)
{
    int tid = threadIdx.x;
    int w = tid >> 5, lane = tid & 31;
    int g = lane >> 2, c = lane & 3;
    int wm = (w & 1) * 16, wn = (w >> 1) * 16;   // 2m x 4n warps over 32x64

    float acc[2][2][4];
    #pragma unroll
    for (int i = 0; i < 2; i++)
        #pragma unroll
        for (int k = 0; k < 2; k++)
            #pragma unroll
            for (int r = 0; r < 4; r++) acc[i][k][r] = 0.f;

    #pragma unroll
    for (int s = 0; s < NSTG-1; s++)
        tile_loads(As, Bs, Ab, Wt, s, m0, n0, s*64, tid);

    for (int it = 0; it < NIT; it++) {
        int buf = it % NSTG;
        asm volatile("cp.async.wait_group %0;" :: "n"(NSTG-2));
        __syncthreads();
        if (it + NSTG-1 < NIT)
            tile_loads(As, Bs, Ab, Wt, (it+NSTG-1) % NSTG,
                       m0, n0, (it+NSTG-1)*64, tid);
        else
            asm volatile("cp.async.commit_group;");

        unsigned af[2][4], bf[2][2][2][2];
        frag_loads(As, Bs, af[0], bf[0], buf, 0, wm, wn, g, c);
        #pragma unroll
        for (int kg = 0; kg < 4; kg++) {
            int cur = kg & 1;
            if (kg < 3)
                frag_loads(As, Bs, af[cur^1], bf[cur^1], buf, kg+1, wm, wn, g, c);
            #pragma unroll
            for (int mat = 0; mat < 2; mat++)
                #pragma unroll
                for (int nt = 0; nt < 2; nt++)
                    mma16(acc[mat][nt], af[cur], bf[cur][mat][nt]);
        }
    }

    #pragma unroll
    for (int nt = 0; nt < 2; nt++)
        #pragma unroll
        for (int r = 0; r < 4; r++) {
            int row = m0 + wm + g + ((r >> 1) << 3);
            int col = n0 + wn + nt*8 + 2*c + (r & 1);
            if (col < H) {
                float cv = acc[0][nt][r];
                float hv = acc[1][nt][r];
                if (bias) {
                    cv += bias[(size_t)row*H2 + col];
                    hv += bias[(size_t)row*H2 + H + col];
                }
                float sp = Spf[(size_t)row*SP + col];
                float o = sp + sigf(cv) * (apply_act(hv, act) - sp);
                Of[(size_t)row*SP + col] = o;
                Ob[(size_t)row*SP + col] = __float2bfloat16(o);
            }
        }
}

// ---- persistent whole-recurrence kernel, 3 CTAs/SM ----
__global__ void __launch_bounds__(256, 3) rnn_persist(
    const float* __restrict__ h0, float* __restrict__ out)
{
    extern __shared__ unsigned dsm[];
    unsigned (*As)[32][36]    = (unsigned(*)[32][36])dsm;
    unsigned (*Bs)[2][64][36] = (unsigned(*)[2][64][36])(dsm + NSTG*32*36);

    const unsigned NB = gridDim.x;
    const int tid = threadIdx.x;

    const int l_start[5] = {0,1,2,5,7};
    const int l_cnt[5]   = {1,1,3,2,2};
    const int st_a[9]   = {-1,0,1,1,1,2,3,5,5};
    const int st_w[9]   = {-1,0,1,2,3,4,6,5,7};
    const int st_o[9]   = {0,1,2,3,4,5,7,6,8};
    const int st_act[9] = {ACT_TANH,ACT_SIG,ACT_RELU,ACT_RELU,ACT_ID,
                           ACT_TANH,ACT_TANH,ACT_SIG,ACT_RELU};

    for (int i = blockIdx.x*256 + tid; i < BH; i += NB*256) {
        int pi = (i/H)*SP + (i%H);
        float v = h0[i];
        g_Hprev[pi] = v;
        g_Hb[pi] = __float2bfloat16(v);
    }
    gsync(NB);

    for (int t = 0; t < TT; t++) {
        for (int lvl = 0; lvl < 5; lvl++) {
            int base = l_start[lvl];
            int njobs = l_cnt[lvl] * TJ;
            for (int job = blockIdx.x; job < njobs; job += NB) {
                int si = base + job / TJ;
                int r  = job % TJ;
                int m0 = (r / 14) * 32;
                int n0 = (r % 14) * 64;
                const __nv_bfloat16* Ab = (st_a[si] < 0) ? g_Hb : g_Sb[st_a[si]];
                const float* Spf = (st_a[si] < 0) ? g_Hprev : g_S[st_a[si]];
                const __nv_bfloat16* Wt = g_Wt[st_w[si] + 1];
                const float* bias = (st_a[si] < 0) ? (g_XW + (size_t)t*BB*H2) : nullptr;
                do_tile(As, Bs, Ab, Spf, Wt, g_S[st_o[si]], g_Sb[st_o[si]],
                        bias, st_act[si], m0, n0);
            }
            gsync(NB);
        }
        float* od = out + (size_t)t*BH;
        for (int i = blockIdx.x*256 + tid; i < BH; i += NB*256) {
            int pi = (i/H)*SP + (i%H);
            float s = g_S[1][pi] + g_S[2][pi] + g_S[3][pi] + g_S[4][pi]
                    + g_S[5][pi] + g_S[6][pi] + g_S[7][pi] + g_S[8][pi];
            s *= 0.125f;
            od[i] = s;
            g_Hprev[pi] = s;
            g_Hb[pi] = __float2bfloat16(s);
            if (t == TT-1) out[(size_t)TT*BH + i] = s;
        }
        gsync(NB);
    }
}

extern "C" void kernel_launch(void* const* d_in, const int* in_sizes, int n_in,
                              void* d_out, int out_size) {
    const float* X   = (const float*)d_in[0];
    const float* h0  = (const float*)d_in[1];
    const float* W0U = (const float*)d_in[2];
    const float* W0s = (const float*)d_in[3];
    const float* W0V = (const float*)d_in[4];
    const float* WsU = (const float*)d_in[5];
    const float* Wss = (const float*)d_in[6];
    const float* WsV = (const float*)d_in[7];
    float* out = (float*)d_out;

    const int smem_bytes = (NSTG*32*36 + NSTG*2*64*36) * 4;   // 69120
    static int attr_done = 0;
    if (!attr_done) {
        cudaFuncSetAttribute(rnn_persist,
            cudaFuncAttributeMaxDynamicSharedMemorySize, smem_bytes);
        attr_done = 1;
    }

    fuse_mma<<<dim3(27,14,1), 256>>>(0, W0U, W0s, W0V);
    fuse_mma<<<dim3(27,7,8),  256>>>(1, WsU, Wss, WsV);
    xw_mma<<<dim3(27,256,1), 256>>>(X);
    rnn_persist<<<NBLK, 256, smem_bytes>>>(h0, out);
}

// round 16
// speedup vs baseline: 1.9917x; 1.0791x over previous
#include <cuda_runtime.h>
#include <cuda_bf16.h>
#include <math.h>

#define H    850
#define H2   1700
#define BB   256
#define TT   128
#define BH   (BB*H)
#define SP   896
#define NIT  14           // K iterations at BK=64
#define NSTG 3
#define NBLK 444
#define TJ   112          // tiles per GEMM (8 m-blocks x 14 n-blocks)

__device__ float g_W0x[H*H2];
__device__ __nv_bfloat16 g_Wt[9][1792*896];   // fused weights, bf16, [n][k]
__device__ float g_XW[(size_t)TT*BB*H2];
__device__ float g_S[9][BB*SP];
__device__ __nv_bfloat16 g_Sb[9][BB*SP];
__device__ float g_Hprev[BB*SP];
__device__ __nv_bfloat16 g_Hb[BB*SP];

__device__ unsigned g_cnt8[8*32];
__device__ unsigned g_master;
__device__ volatile unsigned g_gen;

__device__ __forceinline__ unsigned tf32(float x) {
    unsigned r; asm("cvt.rna.tf32.f32 %0, %1;" : "=r"(r) : "f"(x)); return r;
}
__device__ __forceinline__ void mma8(float* d, const unsigned* a, const unsigned* b) {
    asm("mma.sync.aligned.m16n8k8.row.col.f32.tf32.tf32.f32 "
        "{%0,%1,%2,%3}, {%4,%5,%6,%7}, {%8,%9}, {%0,%1,%2,%3};"
        : "+f"(d[0]), "+f"(d[1]), "+f"(d[2]), "+f"(d[3])
        : "r"(a[0]), "r"(a[1]), "r"(a[2]), "r"(a[3]), "r"(b[0]), "r"(b[1]));
}
__device__ __forceinline__ void mma16(float* d, const unsigned* a, const unsigned* b) {
    asm("mma.sync.aligned.m16n8k16.row.col.f32.bf16.bf16.f32 "
        "{%0,%1,%2,%3}, {%4,%5,%6,%7}, {%8,%9}, {%0,%1,%2,%3};"
        : "+f"(d[0]), "+f"(d[1]), "+f"(d[2]), "+f"(d[3])
        : "r"(a[0]), "r"(a[1]), "r"(a[2]), "r"(a[3]), "r"(b[0]), "r"(b[1]));
}
__device__ __forceinline__ void cp16(void* dst, const void* src) {
    unsigned u = (unsigned)__cvta_generic_to_shared(dst);
    asm volatile("cp.async.cg.shared.global [%0], [%1], 16;" :: "r"(u), "l"(src));
}
__device__ __forceinline__ void ldm4(unsigned& r0, unsigned& r1, unsigned& r2,
                                     unsigned& r3, unsigned addr) {
    asm volatile("ldmatrix.sync.aligned.m8n8.x4.shared.b16 {%0,%1,%2,%3}, [%4];"
        : "=r"(r0), "=r"(r1), "=r"(r2), "=r"(r3) : "r"(addr));
}

#define ACT_TANH 0
#define ACT_RELU 1
#define ACT_SIG  2
#define ACT_ID   3
__device__ __forceinline__ float apply_act(float x, int a) {
    switch (a) {
        case ACT_TANH: return tanhf(x);
        case ACT_RELU: return fmaxf(x, 0.f);
        case ACT_SIG:  return 1.f / (1.f + expf(-x));
        default:       return x;
    }
}
__device__ __forceinline__ float sigf(float x) { return 1.f / (1.f + expf(-x)); }

// ---- tf32 weight fusion; writes g_W0x (fp32) and g_Wt (bf16 [n][k]) ----
__global__ void __launch_bounds__(256) fuse_mma(
    int mode, const float* __restrict__ A, const float* __restrict__ Sig,
    const float* __restrict__ Bx)
{
    __shared__ unsigned As[128][17];
    __shared__ unsigned Bs[16][65];

    int z = blockIdx.z;
    int M = mode ? H : H2;
    int K = M, lda = M;
    const float* Ap = A;
    const float* Sp = Sig;
    const float* Bp = Bx;
    if (mode == 1) { Ap = A + (size_t)z*H*H; Sp = Sig + z*H; Bp = Bx + (size_t)z*H2*H2; }

    int tid = threadIdx.x;
    int w = tid >> 5, lane = tid & 31;
    int g = lane >> 2, c = lane & 3;
    int wm = (w & 3) * 32, wn = (w >> 2) * 32;
    int m0 = blockIdx.y << 7, n0 = blockIdx.x << 6;

    float acc[2][4][4];
    #pragma unroll
    for (int i = 0; i < 2; i++)
        #pragma unroll
        for (int j = 0; j < 4; j++)
            #pragma unroll
            for (int r = 0; r < 4; r++) acc[i][j][r] = 0.f;

    for (int kt = 0; kt < K; kt += 16) {
        #pragma unroll
        for (int i = 0; i < 8; i++) {
            int idx = tid + (i << 8);
            int am = idx >> 4, ak = idx & 15;
            int gm = m0 + am, gk = kt + ak;
            As[am][ak] = (gm < M && gk < K) ? tf32(Ap[(size_t)gm*lda + gk] * Sp[gk]) : 0u;
        }
        #pragma unroll
        for (int i = 0; i < 4; i++) {
            int idx = tid + (i << 8);
            int bk = idx >> 6, bn = idx & 63;
            int gk = kt + bk, gn = n0 + bn;
            Bs[bk][bn] = (gk < K && gn < H2) ? tf32(Bp[(size_t)gk*H2 + gn]) : 0u;
        }
        __syncthreads();
        #pragma unroll
        for (int k8 = 0; k8 < 16; k8 += 8) {
            unsigned af[2][4], bf[4][2];
            #pragma unroll
            for (int mt = 0; mt < 2; mt++) {
                int R = wm + mt*16;
                af[mt][0] = As[R+g][k8+c];
                af[mt][1] = As[R+g+8][k8+c];
                af[mt][2] = As[R+g][k8+c+4];
                af[mt][3] = As[R+g+8][k8+c+4];
            }
            #pragma unroll
            for (int nt = 0; nt < 4; nt++) {
                int Nb = wn + nt*8;
                bf[nt][0] = Bs[k8+c][Nb+g];
                bf[nt][1] = Bs[k8+c+4][Nb+g];
            }
            #pragma unroll
            for (int mt = 0; mt < 2; mt++)
                #pragma unroll
                for (int nt = 0; nt < 4; nt++)
                    mma8(acc[mt][nt], af[mt], bf[nt]);
        }
        __syncthreads();
    }

    #pragma unroll
    for (int mt = 0; mt < 2; mt++)
        #pragma unroll
        for (int nt = 0; nt < 4; nt++)
            #pragma unroll
            for (int r = 0; r < 4; r++) {
                int row = m0 + wm + mt*16 + g + ((r >> 1) << 3);
                int col = n0 + wn + nt*8 + 2*c + (r & 1);
                if (col >= H2 || row >= M) continue;
                float v = acc[mt][nt][r];
                if (mode == 0) {
                    if (row < H) { g_W0x[row*H2 + col] = v; continue; }
                    int k = row - H;
                    int n = (col < H) ? col : (896 + col - H);
                    g_Wt[0][(size_t)n*896 + k] = __float2bfloat16(v);
                } else {
                    int n = (col < H) ? col : (896 + col - H);
                    g_Wt[z+1][(size_t)n*896 + row] = __float2bfloat16(v);
                }
            }
}

// ---- tf32 XW precompute ----
__global__ void __launch_bounds__(256) xw_mma(const float* __restrict__ X)
{
    __shared__ unsigned As[128][17];
    __shared__ unsigned Bs[16][65];

    int tid = threadIdx.x;
    int w = tid >> 5, lane = tid & 31;
    int g = lane >> 2, c = lane & 3;
    int wm = (w & 3) * 32, wn = (w >> 2) * 32;
    int m0 = blockIdx.y << 7, n0 = blockIdx.x << 6;

    float acc[2][4][4];
    #pragma unroll
    for (int i = 0; i < 2; i++)
        #pragma unroll
        for (int j = 0; j < 4; j++)
            #pragma unroll
            for (int r = 0; r < 4; r++) acc[i][j][r] = 0.f;

    for (int kt = 0; kt < H; kt += 16) {
        #pragma unroll
        for (int i = 0; i < 8; i++) {
            int idx = tid + (i << 8);
            int am = idx >> 4, ak = idx & 15;
            int gk = kt + ak;
            As[am][ak] = (gk < H) ? tf32(X[(size_t)(m0+am)*H + gk]) : 0u;
        }
        #pragma unroll
        for (int i = 0; i < 4; i++) {
            int idx = tid + (i << 8);
            int bk = idx >> 6, bn = idx & 63;
            int gk = kt + bk, gn = n0 + bn;
            Bs[bk][bn] = (gk < H && gn < H2) ? tf32(g_W0x[(size_t)gk*H2 + gn]) : 0u;
        }
        __syncthreads();
        #pragma unroll
        for (int k8 = 0; k8 < 16; k8 += 8) {
            unsigned af[2][4], bf[4][2];
            #pragma unroll
            for (int mt = 0; mt < 2; mt++) {
                int R = wm + mt*16;
                af[mt][0] = As[R+g][k8+c];
                af[mt][1] = As[R+g+8][k8+c];
                af[mt][2] = As[R+g][k8+c+4];
                af[mt][3] = As[R+g+8][k8+c+4];
            }
            #pragma unroll
            for (int nt = 0; nt < 4; nt++) {
                int Nb = wn + nt*8;
                bf[nt][0] = Bs[k8+c][Nb+g];
                bf[nt][1] = Bs[k8+c+4][Nb+g];
            }
            #pragma unroll
            for (int mt = 0; mt < 2; mt++)
                #pragma unroll
                for (int nt = 0; nt < 4; nt++)
                    mma8(acc[mt][nt], af[mt], bf[nt]);
        }
        __syncthreads();
    }

    #pragma unroll
    for (int mt = 0; mt < 2; mt++)
        #pragma unroll
        for (int nt = 0; nt < 4; nt++)
            #pragma unroll
            for (int r = 0; r < 4; r++) {
                int row = m0 + wm + mt*16 + g + ((r >> 1) << 3);
                int col = n0 + wn + nt*8 + 2*c + (r & 1);
                if (col < H2) g_XW[(size_t)row*H2 + col] = acc[mt][nt][r];
            }
}

// ---- hierarchical device-wide barrier ----
__device__ __forceinline__ void gsync(unsigned NB) {
    __syncthreads();
    if (threadIdx.x == 0) {
        __threadfence();
        unsigned my = g_gen;
        unsigned grp = blockIdx.x & 7;
        unsigned cnt = (NB - grp + 7) >> 3;
        if (atomicAdd(&g_cnt8[grp*32], 1u) == cnt - 1) {
            g_cnt8[grp*32] = 0;
            __threadfence();
            if (atomicAdd(&g_master, 1u) == 7) {
                g_master = 0;
                __threadfence();
                g_gen = my + 1;
            }
        }
        while (g_gen == my) __nanosleep(32);
        __threadfence();
    }
    __syncthreads();
}

// ---- bf16 32x64 (c&h) tile, BK=64, 3-stage pipeline, ldmatrix frags ----
// As: [NSTG][32][36] u32 (bf16x2), Bs: [NSTG][2][64][36]
#define A_STAGE (32*36*4)
#define B_STAGE (2*64*36*4)
#define B_MAT   (64*36*4)

__device__ __forceinline__ void tile_loads(
    unsigned (*As)[32][36], unsigned (*Bs)[2][64][36],
    const __nv_bfloat16* Ab, const __nv_bfloat16* Wt,
    int b, int m0, int n0, int kt, int tid)
{
    {
        int row = tid >> 3, q = tid & 7;
        cp16(&As[b][row][q*4], Ab + (size_t)(m0+row)*SP + kt + q*8);
    }
    #pragma unroll
    for (int i = 0; i < 4; i++) {
        int idx = tid + (i << 8);
        int mat = idx >> 9, rem = idx & 511;
        int row = rem >> 3, q = rem & 7;
        cp16(&Bs[b][mat][row][q*4],
             Wt + (size_t)(n0 + row + mat*896)*896 + kt + q*8);
    }
    asm volatile("cp.async.commit_group;");
}

__device__ __forceinline__ void do_tile(
    unsigned (*As)[32][36], unsigned (*Bs)[2][64][36],
    const __nv_bfloat16* __restrict__ Ab, const float* __restrict__ Spf,
    const __nv_bfloat16* __restrict__ Wt, float* __restrict__ Of,
    __nv_bfloat16* __restrict__ Ob, const float* __restrict__ bias,
    int act, int m0, int n0)
{
    int tid = threadIdx.x;
    int w = tid >> 5, lane = tid & 31;
    int g = lane >> 2, c = lane & 3;
    int wm = (w & 1) * 16, wn = (w >> 1) * 16;

    // per-lane ldmatrix base offsets (bytes)
    int lrow = lane & 15;
    int lko  = (lane >> 4) * 16;
    unsigned aBase = (unsigned)__cvta_generic_to_shared(&As[0][0][0])
                   + (wm + lrow) * 144 + lko;
    unsigned bBase = (unsigned)__cvta_generic_to_shared(&Bs[0][0][0][0])
                   + (wn + lrow) * 144 + lko;

    float acc[2][2][4];
    #pragma unroll
    for (int i = 0; i < 2; i++)
        #pragma unroll
        for (int k = 0; k < 2; k++)
            #pragma unroll
            for (int r = 0; r < 4; r++) acc[i][k][r] = 0.f;

    #pragma unroll
    for (int s = 0; s < NSTG-1; s++)
        tile_loads(As, Bs, Ab, Wt, s, m0, n0, s*64, tid);

    for (int it = 0; it < NIT; it++) {
        int buf = it % NSTG;
        asm volatile("cp.async.wait_group %0;" :: "n"(NSTG-2));
        __syncthreads();
        if (it + NSTG-1 < NIT)
            tile_loads(As, Bs, Ab, Wt, (it+NSTG-1) % NSTG,
                       m0, n0, (it+NSTG-1)*64, tid);
        else
            asm volatile("cp.async.commit_group;");

        unsigned aA = aBase + buf*A_STAGE;
        unsigned aB = bBase + buf*B_STAGE;

        unsigned af[2][4], bf[2][2][2][2];
        ldm4(af[0][0], af[0][1], af[0][2], af[0][3], aA);
        ldm4(bf[0][0][0][0], bf[0][0][1][0], bf[0][0][0][1], bf[0][0][1][1], aB);
        ldm4(bf[0][1][0][0], bf[0][1][1][0], bf[0][1][0][1], bf[0][1][1][1], aB + B_MAT);

        #pragma unroll
        for (int kg = 0; kg < 4; kg++) {
            int cur = kg & 1;
            if (kg < 3) {
                int nx = cur ^ 1;
                unsigned ko = (kg+1) * 32;
                ldm4(af[nx][0], af[nx][1], af[nx][2], af[nx][3], aA + ko);
                ldm4(bf[nx][0][0][0], bf[nx][0][1][0], bf[nx][0][0][1], bf[nx][0][1][1],
                     aB + ko);
                ldm4(bf[nx][1][0][0], bf[nx][1][1][0], bf[nx][1][0][1], bf[nx][1][1][1],
                     aB + B_MAT + ko);
            }
            #pragma unroll
            for (int mat = 0; mat < 2; mat++)
                #pragma unroll
                for (int nt = 0; nt < 2; nt++)
                    mma16(acc[mat][nt], af[cur], bf[cur][mat][nt]);
        }
    }

    #pragma unroll
    for (int nt = 0; nt < 2; nt++)
        #pragma unroll
        for (int r = 0; r < 4; r++) {
            int row = m0 + wm + g + ((r >> 1) << 3);
            int col = n0 + wn + nt*8 + 2*c + (r & 1);
            if (col < H) {
                float cv = acc[0][nt][r];
                float hv = acc[1][nt][r];
                if (bias) {
                    cv += bias[(size_t)row*H2 + col];
                    hv += bias[(size_t)row*H2 + H + col];
                }
                float sp = Spf[(size_t)row*SP + col];
                float o = sp + sigf(cv) * (apply_act(hv, act) - sp);
                Of[(size_t)row*SP + col] = o;
                Ob[(size_t)row*SP + col] = __float2bfloat16(o);
            }
        }
}

// ---- persistent whole-recurrence kernel, 3 CTAs/SM ----
__global__ void __launch_bounds__(256, 3) rnn_persist(
    const float* __restrict__ h0, float* __restrict__ out)
{
    extern __shared__ unsigned dsm[];
    unsigned (*As)[32][36]    = (unsigned(*)[32][36])dsm;
    unsigned (*Bs)[2][64][36] = (unsigned(*)[2][64][36])(dsm + NSTG*32*36);

    const unsigned NB = gridDim.x;
    const int tid = threadIdx.x;

    const int l_start[5] = {0,1,2,5,7};
    const int l_cnt[5]   = {1,1,3,2,2};
    const int st_a[9]   = {-1,0,1,1,1,2,3,5,5};
    const int st_w[9]   = {-1,0,1,2,3,4,6,5,7};
    const int st_o[9]   = {0,1,2,3,4,5,7,6,8};
    const int st_act[9] = {ACT_TANH,ACT_SIG,ACT_RELU,ACT_RELU,ACT_ID,
                           ACT_TANH,ACT_TANH,ACT_SIG,ACT_RELU};

    for (int i = blockIdx.x*256 + tid; i < BH; i += NB*256) {
        int pi = (i/H)*SP + (i%H);
        float v = h0[i];
        g_Hprev[pi] = v;
        g_Hb[pi] = __float2bfloat16(v);
    }
    gsync(NB);

    for (int t = 0; t < TT; t++) {
        for (int lvl = 0; lvl < 5; lvl++) {
            int base = l_start[lvl];
            int njobs = l_cnt[lvl] * TJ;
            for (int job = blockIdx.x; job < njobs; job += NB) {
                int si = base + job / TJ;
                int r  = job % TJ;
                int m0 = (r / 14) * 32;
                int n0 = (r % 14) * 64;
                const __nv_bfloat16* Ab = (st_a[si] < 0) ? g_Hb : g_Sb[st_a[si]];
                const float* Spf = (st_a[si] < 0) ? g_Hprev : g_S[st_a[si]];
                const __nv_bfloat16* Wt = g_Wt[st_w[si] + 1];
                const float* bias = (st_a[si] < 0) ? (g_XW + (size_t)t*BB*H2) : nullptr;
                do_tile(As, Bs, Ab, Spf, Wt, g_S[st_o[si]], g_Sb[st_o[si]],
                        bias, st_act[si], m0, n0);
            }
            gsync(NB);
        }
        float* od = out + (size_t)t*BH;
        for (int i = blockIdx.x*256 + tid; i < BH; i += NB*256) {
            int pi = (i/H)*SP + (i%H);
            float s = g_S[1][pi] + g_S[2][pi] + g_S[3][pi] + g_S[4][pi]
                    + g_S[5][pi] + g_S[6][pi] + g_S[7][pi] + g_S[8][pi];
            s *= 0.125f;
            od[i] = s;
            g_Hprev[pi] = s;
            g_Hb[pi] = __float2bfloat16(s);
            if (t == TT-1) out[(size_t)TT*BH + i] = s;
        }
        gsync(NB);
    }
}

extern "C" void kernel_launch(void* const* d_in, const int* in_sizes, int n_in,
                              void* d_out, int out_size) {
    const float* X   = (const float*)d_in[0];
    const float* h0  = (const float*)d_in[1];
    const float* W0U = (const float*)d_in[2];
    const float* W0s = (const float*)d_in[3];
    const float* W0V = (const float*)d_in[4];
    const float* WsU = (const float*)d_in[5];
    const float* Wss = (const float*)d_in[6];
    const float* WsV = (const float*)d_in[7];
    float* out = (float*)d_out;

    const int smem_bytes = (NSTG*32*36 + NSTG*2*64*36) * 4;   // 69120
    static int attr_done = 0;
    if (!attr_done) {
        cudaFuncSetAttribute(rnn_persist,
            cudaFuncAttributeMaxDynamicSharedMemorySize, smem_bytes);
        attr_done = 1;
    }

    fuse_mma<<<dim3(27,14,1), 256>>>(0, W0U, W0s, W0V);
    fuse_mma<<<dim3(27,7,8),  256>>>(1, WsU, Wss, WsV);
    xw_mma<<<dim3(27,256,1), 256>>>(X);
    rnn_persist<<<NBLK, 256, smem_bytes>>>(h0, out);
}